// round 2
// baseline (speedup 1.0000x reference)
#include <cuda_runtime.h>

// Weighted BCE loss, mean-reduced.
// loss_i = (t_i==1) ? -log(o_i + eps) : -8 * log(1 - o_i + eps);  out = mean(loss)

#define POS_WEIGHT 1.0f
#define NEG_WEIGHT 8.0f
#define BCE_EPS    1e-7f

#define NBLOCKS  2048
#define NTHREADS 256

__device__ float g_partials[NBLOCKS];

__device__ __forceinline__ float bce_elem(float o, int t) {
    // branchless select between the two weighted -log terms
    float pos = -__logf(o + BCE_EPS);
    float neg = -NEG_WEIGHT * __logf(1.0f - o + BCE_EPS);
    return (t == 1) ? pos : neg;
}

__global__ void __launch_bounds__(NTHREADS)
bce_partial_kernel(const float4* __restrict__ out4,
                   const int4*   __restrict__ tgt4,
                   const float*  __restrict__ out_s,
                   const int*    __restrict__ tgt_s,
                   int n4, int n)
{
    float acc = 0.0f;
    int idx    = blockIdx.x * blockDim.x + threadIdx.x;
    int stride = gridDim.x * blockDim.x;

    for (int i = idx; i < n4; i += stride) {
        float4 o = out4[i];
        int4   t = tgt4[i];
        acc += bce_elem(o.x, t.x);
        acc += bce_elem(o.y, t.y);
        acc += bce_elem(o.z, t.z);
        acc += bce_elem(o.w, t.w);
    }

    // scalar tail (n not divisible by 4) — handled by thread 0 of block 0
    if (idx == 0) {
        for (int i = n4 * 4; i < n; i++)
            acc += bce_elem(out_s[i], tgt_s[i]);
    }

    // warp reduce
    #pragma unroll
    for (int off = 16; off > 0; off >>= 1)
        acc += __shfl_down_sync(0xffffffffu, acc, off);

    __shared__ float s_warp[NTHREADS / 32];
    if ((threadIdx.x & 31) == 0)
        s_warp[threadIdx.x >> 5] = acc;
    __syncthreads();

    if (threadIdx.x < 32) {
        float v = (threadIdx.x < NTHREADS / 32) ? s_warp[threadIdx.x] : 0.0f;
        #pragma unroll
        for (int off = 16; off > 0; off >>= 1)
            v += __shfl_down_sync(0xffffffffu, v, off);
        if (threadIdx.x == 0)
            g_partials[blockIdx.x] = v;
    }
}

__global__ void __launch_bounds__(1024)
bce_final_kernel(float* __restrict__ out, int n)
{
    double acc = 0.0;
    for (int i = threadIdx.x; i < NBLOCKS; i += blockDim.x)
        acc += (double)g_partials[i];

    // warp reduce (double)
    #pragma unroll
    for (int off = 16; off > 0; off >>= 1)
        acc += __shfl_down_sync(0xffffffffu, acc, off);

    __shared__ double s_warp[32];
    if ((threadIdx.x & 31) == 0)
        s_warp[threadIdx.x >> 5] = acc;
    __syncthreads();

    if (threadIdx.x < 32) {
        double v = (threadIdx.x < (int)(blockDim.x / 32)) ? s_warp[threadIdx.x] : 0.0;
        #pragma unroll
        for (int off = 16; off > 0; off >>= 1)
            v += __shfl_down_sync(0xffffffffu, v, off);
        if (threadIdx.x == 0)
            out[0] = (float)(v / (double)n);
    }
}

extern "C" void kernel_launch(void* const* d_in, const int* in_sizes, int n_in,
                              void* d_out, int out_size)
{
    const float* outputs = (const float*)d_in[0];
    const int*   targets = (const int*)d_in[1];
    float* out = (float*)d_out;

    int n  = in_sizes[0];
    int n4 = n >> 2;

    bce_partial_kernel<<<NBLOCKS, NTHREADS>>>(
        (const float4*)outputs, (const int4*)targets,
        outputs, targets, n4, n);
    bce_final_kernel<<<1, 1024>>>(out, n);
}

// round 5
// speedup vs baseline: 1.0887x; 1.0887x over previous
#include <cuda_runtime.h>

// Weighted BCE loss, mean-reduced, single fused kernel.
// loss_i = (t_i==1) ? -log(o_i + eps) : -8 * log(1 - o_i + eps);  out = mean(loss)

#define NEG_WEIGHT 8.0f
#define BCE_EPS    1e-7f

#define NBLOCKS  2048
#define NTHREADS 256

__device__ double       g_acc;    // zero-init; reset by last block each launch
__device__ unsigned int g_count;  // zero-init; reset by last block each launch

__device__ __forceinline__ float bce_elem(float o, int t) {
    // one log per element: x = t ? o : 1-o ; w = t ? 1 : 8
    float x = (t == 1) ? o : (1.0f - o);
    float w = (t == 1) ? 1.0f : NEG_WEIGHT;
    return w * (-__logf(x + BCE_EPS));
}

__global__ void __launch_bounds__(NTHREADS)
bce_fused_kernel(const float4* __restrict__ out4,
                 const int4*   __restrict__ tgt4,
                 const float*  __restrict__ out_s,
                 const int*    __restrict__ tgt_s,
                 float* __restrict__ result,
                 int n4, int n)
{
    float acc = 0.0f;
    int idx    = blockIdx.x * blockDim.x + threadIdx.x;
    int stride = gridDim.x * blockDim.x;

    for (int i = idx; i < n4; i += stride) {
        float4 o = out4[i];
        int4   t = tgt4[i];
        acc += bce_elem(o.x, t.x);
        acc += bce_elem(o.y, t.y);
        acc += bce_elem(o.z, t.z);
        acc += bce_elem(o.w, t.w);
    }

    // scalar tail (n not divisible by 4)
    if (idx == 0) {
        for (int i = n4 * 4; i < n; i++)
            acc += bce_elem(out_s[i], tgt_s[i]);
    }

    // intra-block reduction: warp shuffle, then smem across warps
    #pragma unroll
    for (int off = 16; off > 0; off >>= 1)
        acc += __shfl_down_sync(0xffffffffu, acc, off);

    __shared__ float s_warp[NTHREADS / 32];
    if ((threadIdx.x & 31) == 0)
        s_warp[threadIdx.x >> 5] = acc;
    __syncthreads();

    if (threadIdx.x == 0) {
        float bsum = 0.0f;
        #pragma unroll
        for (int w = 0; w < NTHREADS / 32; w++)
            bsum += s_warp[w];

        // cross-block accumulation in double, last block finalizes
        atomicAdd(&g_acc, (double)bsum);
        __threadfence();
        unsigned int old = atomicAdd(&g_count, 1u);
        if (old == gridDim.x - 1) {
            double total = g_acc;
            result[0] = (float)(total / (double)n);
            // reset for next graph replay
            g_acc   = 0.0;
            g_count = 0u;
            __threadfence();
        }
    }
}

extern "C" void kernel_launch(void* const* d_in, const int* in_sizes, int n_in,
                              void* d_out, int out_size)
{
    const float* outputs = (const float*)d_in[0];
    const int*   targets = (const int*)d_in[1];
    float* out = (float*)d_out;

    int n  = in_sizes[0];
    int n4 = n >> 2;

    bce_fused_kernel<<<NBLOCKS, NTHREADS>>>(
        (const float4*)outputs, (const int4*)targets,
        outputs, targets, out, n4, n);
}